// round 14
// baseline (speedup 1.0000x reference)
#include <cuda_runtime.h>
#include <cuda_bf16.h>
#include <cuda_fp16.h>
#include <cstdint>

// B=4, N=16384 (128x128), C=256, heads=8, hd=32, window=8 (64 tokens/window)
#define BATCH 4
#define NTOK  16384
#define CDIM  256
#define MROWS (BATCH * NTOK)   // 65536
#define HGRID 128
#define NHEAD 8
#define HD    32
#define WS    8
#define NWIN  256

typedef unsigned long long u64;
typedef unsigned int u32;
typedef __nv_bfloat16 bf16;
typedef __half f16;

// ---------------------------------------------------------------------------
// sm80-class tensor-core helpers (valid on plain sm_103 PTX target)
// ---------------------------------------------------------------------------
__device__ __forceinline__ u32 smem_u32(const void* p) {
    u32 a; asm("{ .reg .u64 t; cvta.to.shared.u64 t, %1; cvt.u32.u64 %0, t; }"
               : "=r"(a) : "l"(p));
    return a;
}
__device__ __forceinline__ void cp16(u32 s, const void* g) {
    asm volatile("cp.async.cg.shared.global [%0], [%1], 16;" :: "r"(s), "l"(g));
}
#define CP_COMMIT() asm volatile("cp.async.commit_group;" ::: "memory")
#define CP_WAIT(n)  asm volatile("cp.async.wait_group %0;" :: "n"(n) : "memory")

__device__ __forceinline__ void ldmA(u32* a, u32 addr) {
    asm volatile("ldmatrix.sync.aligned.m8n8.x4.shared.b16 {%0,%1,%2,%3}, [%4];"
        : "=r"(a[0]), "=r"(a[1]), "=r"(a[2]), "=r"(a[3]) : "r"(addr));
}
__device__ __forceinline__ void ldmB(u32* b, u32 addr) {
    asm volatile("ldmatrix.sync.aligned.m8n8.x2.shared.b16 {%0,%1}, [%2];"
        : "=r"(b[0]), "=r"(b[1]) : "r"(addr));
}
__device__ __forceinline__ void ldmBT(u32* b, u32 addr) {
    asm volatile("ldmatrix.sync.aligned.m8n8.x2.trans.shared.b16 {%0,%1}, [%2];"
        : "=r"(b[0]), "=r"(b[1]) : "r"(addr));
}
// bf16 mma (attention)
__device__ __forceinline__ void mma16816(float* d, const u32* a, const u32* b) {
    asm volatile("mma.sync.aligned.m16n8k16.row.col.f32.bf16.bf16.f32 "
        "{%0,%1,%2,%3}, {%4,%5,%6,%7}, {%8,%9}, {%0,%1,%2,%3};"
        : "+f"(d[0]), "+f"(d[1]), "+f"(d[2]), "+f"(d[3])
        : "r"(a[0]), "r"(a[1]), "r"(a[2]), "r"(a[3]), "r"(b[0]), "r"(b[1]));
}
// fp16 mma (projections)
__device__ __forceinline__ void mma16816h(float* d, const u32* a, const u32* b) {
    asm volatile("mma.sync.aligned.m16n8k16.row.col.f32.f16.f16.f32 "
        "{%0,%1,%2,%3}, {%4,%5,%6,%7}, {%8,%9}, {%0,%1,%2,%3};"
        : "+f"(d[0]), "+f"(d[1]), "+f"(d[2]), "+f"(d[3])
        : "r"(a[0]), "r"(a[1]), "r"(a[2]), "r"(a[3]), "r"(b[0]), "r"(b[1]));
}

// split two floats into packed bf16 hi and lo words
__device__ __forceinline__ void split2(float x0, float x1, u32 &h, u32 &l) {
    bf16 h0 = __float2bfloat16(x0), h1 = __float2bfloat16(x1);
    bf16 l0 = __float2bfloat16(x0 - __bfloat162float(h0));
    bf16 l1 = __float2bfloat16(x1 - __bfloat162float(h1));
    __nv_bfloat162 hp; hp.x = h0; hp.y = h1;
    __nv_bfloat162 lp; lp.x = l0; lp.y = l1;
    h = *(u32*)&hp; l = *(u32*)&lp;
}
// split two floats into packed fp16 hi and lo words
__device__ __forceinline__ void split2h(float x0, float x1, u32 &h, u32 &l) {
    f16 h0 = __float2half_rn(x0), h1 = __float2half_rn(x1);
    f16 l0 = __float2half_rn(x0 - __half2float(h0));
    f16 l1 = __float2half_rn(x1 - __half2float(h1));
    __half2 hp; hp.x = h0; hp.y = h1;
    __half2 lp; lp.x = l0; lp.y = l1;
    h = *(u32*)&hp; l = *(u32*)&lp;
}

// ---------------------------------------------------------------------------
// Scratch (device globals, 16B-aligned via uint4)
// ---------------------------------------------------------------------------
__device__ uint4 g_qph4[MROWS * CDIM / 8];      // q projection bf16 hi/lo (attn in)
__device__ uint4 g_qpl4[MROWS * CDIM / 8];
__device__ uint4 g_kph4[MROWS * CDIM / 8];
__device__ uint4 g_kpl4[MROWS * CDIM / 8];
__device__ uint4 g_vph4[MROWS * CDIM / 8];
__device__ uint4 g_vpl4[MROWS * CDIM / 8];
__device__ uint4 g_qh4[MROWS * CDIM / 8];       // input q  fp16 hi/lo
__device__ uint4 g_ql4[MROWS * CDIM / 8];
__device__ uint4 g_kvh4[MROWS * CDIM / 8];      // input kv fp16 hi/lo
__device__ uint4 g_kvl4[MROWS * CDIM / 8];
__device__ uint4 g_xah4[MROWS * CDIM / 8];      // attn out fp16 hi/lo
__device__ uint4 g_xal4[MROWS * CDIM / 8];
__device__ uint4 g_w4[4][CDIM * CDIM / 8];      // [which W] single fp16, transposed [n][k]

// ---------------------------------------------------------------------------
// W convert + transpose, single fp16, all 4 weights in one launch
// ---------------------------------------------------------------------------
__global__ void convw_kernel(const float* __restrict__ W0, const float* __restrict__ W1,
                             const float* __restrict__ W2, const float* __restrict__ W3,
                             f16* __restrict__ wt)
{
    const int w = blockIdx.x >> 8, k = blockIdx.x & 255, n = threadIdx.x;
    const float* W = (w == 0) ? W0 : (w == 1) ? W1 : (w == 2) ? W2 : W3;
    f16* wT = wt + (size_t)w * CDIM * CDIM;
    wT[n * CDIM + k] = __float2half_rn(W[k * CDIM + n]);
}

// ---------------------------------------------------------------------------
// A convert: q AND kv in one launch. fp32 -> fp16 hi/lo, 8 floats/thread
// ---------------------------------------------------------------------------
__global__ __launch_bounds__(256) void conv_hilo_kernel(
    const uint4* __restrict__ inq, const uint4* __restrict__ inkv,
    uint4* __restrict__ qh, uint4* __restrict__ ql,
    uint4* __restrict__ kvh, uint4* __restrict__ kvl)
{
    const int which = blockIdx.x >> 13;
    const int i = (blockIdx.x & 8191) * 256 + threadIdx.x;
    const uint4* in = which ? inkv : inq;
    uint4* oh = which ? kvh : qh;
    uint4* ol = which ? kvl : ql;

    uint4 a = in[2 * i], b = in[2 * i + 1];
    float f[8] = {__uint_as_float(a.x), __uint_as_float(a.y),
                  __uint_as_float(a.z), __uint_as_float(a.w),
                  __uint_as_float(b.x), __uint_as_float(b.y),
                  __uint_as_float(b.z), __uint_as_float(b.w)};
    u32 hw[4], lw[4];
#pragma unroll
    for (int p = 0; p < 4; p++) split2h(f[2 * p], f[2 * p + 1], hw[p], lw[p]);
    oh[i] = make_uint4(hw[0], hw[1], hw[2], hw[3]);
    ol[i] = make_uint4(lw[0], lw[1], lw[2], lw[3]);
}

// ---------------------------------------------------------------------------
// fp16 2-pass GEMM: C = (Ah+Al)[M,256] @ B^T + bias, B single fp16.
// CTA 128x128, 8 warps, 2 CTAs/SM. K chunks of 32, cp.async double-buffered,
// 80B rows. Per k16: ldm B, Ah -> Ah*B ; ldm Al -> Al*B  (12 ldm, 32 mma).
// ---------------------------------------------------------------------------
#define KC     32
#define RSTR   80
#define MATSZ  (128 * RSTR)           // 10240
#define OFF_AH 0
#define OFF_AL MATSZ
#define OFF_B  (2 * MATSZ)
#define BUFSZ  (3 * MATSZ)            // 30720
#define GSMEM_TOTAL 69632             // max(2*BUFSZ, epilogue 128*132*4)

template<bool BF16OUT>
__device__ __forceinline__ void gemm_body(
    const f16* __restrict__ Ah, const f16* __restrict__ Al,
    const f16* __restrict__ BT,
    const float* __restrict__ bias,
    float* __restrict__ C, bf16* __restrict__ Ch, bf16* __restrict__ Cl,
    int row0, int col0, char* smem)
{
    const u32 sb = smem_u32(smem);
    const int tid  = threadIdx.x;
    const int lane = tid & 31;
    const int wid  = tid >> 5;
    const int wm   = wid >> 2;
    const int wn   = wid & 3;

    const int st_row = tid >> 1;
    const int st_ch  = (tid & 1) << 4;
    const f16* gA_h = Ah + (size_t)(row0 + st_row) * CDIM + st_ch;
    const f16* gA_l = Al + (size_t)(row0 + st_row) * CDIM + st_ch;
    const f16* gB   = BT + (size_t)(col0 + st_row) * CDIM + st_ch;
    const u32 st_s = st_row * RSTR + st_ch * 2;

    auto stage = [&](int s, int kc) {
        const u32 base = sb + s * BUFSZ + st_s;
        const int gk = kc * KC;
        cp16(base + OFF_AH,      gA_h + gk);
        cp16(base + OFF_AH + 16, gA_h + gk + 8);
        cp16(base + OFF_AL,      gA_l + gk);
        cp16(base + OFF_AL + 16, gA_l + gk + 8);
        cp16(base + OFF_B,       gB + gk);
        cp16(base + OFF_B + 16,  gB + gk + 8);
    };

    float acc[4][4][4];
#pragma unroll
    for (int mt = 0; mt < 4; mt++)
#pragma unroll
        for (int nt = 0; nt < 4; nt++)
#pragma unroll
            for (int e = 0; e < 4; e++) acc[mt][nt][e] = 0.f;

    const u32 aLane = (u32)((wm * 64 + (lane & 15)) * RSTR + ((lane >> 4) << 4));
    const u32 bLane = (u32)((wn * 32 + (lane & 7)) * RSTR + (((lane >> 3) & 1) << 4));

    stage(0, 0); CP_COMMIT();
    stage(1, 1); CP_COMMIT();

#pragma unroll
    for (int kc = 0; kc < 8; kc++) {
        if (kc < 7) CP_WAIT(1); else CP_WAIT(0);
        __syncthreads();

        const u32 sbuf = sb + (kc & 1) * BUFSZ;
#pragma unroll
        for (int k16 = 0; k16 < 2; k16++) {
            const u32 aAddr = sbuf + aLane + k16 * 32;
            const u32 bAddr = sbuf + bLane + k16 * 32;
            u32 ah[4][4], al[4][4], bb[4][2];
#pragma unroll
            for (int nt = 0; nt < 4; nt++) ldmB(bb[nt], bAddr + OFF_B + nt * (8 * RSTR));
#pragma unroll
            for (int mt = 0; mt < 4; mt++) ldmA(ah[mt], aAddr + OFF_AH + mt * (16 * RSTR));
#pragma unroll
            for (int mt = 0; mt < 4; mt++)
#pragma unroll
                for (int nt = 0; nt < 4; nt++) mma16816h(acc[mt][nt], ah[mt], bb[nt]);
#pragma unroll
            for (int mt = 0; mt < 4; mt++) ldmA(al[mt], aAddr + OFF_AL + mt * (16 * RSTR));
#pragma unroll
            for (int mt = 0; mt < 4; mt++)
#pragma unroll
                for (int nt = 0; nt < 4; nt++) mma16816h(acc[mt][nt], al[mt], bb[nt]);
        }
        __syncthreads();
        if (kc < 6) { stage(kc & 1, kc + 2); CP_COMMIT(); }
    }

    // ---- epilogue via smem for coalesced stores (128 x 132 fp32)
    float* cs = (float*)smem;
#pragma unroll
    for (int mt = 0; mt < 4; mt++) {
        const int r = wm * 64 + mt * 16 + (lane >> 2);
#pragma unroll
        for (int nt = 0; nt < 4; nt++) {
            const int c = wn * 32 + nt * 8 + (lane & 3) * 2;
            *(float2*)(cs + r * 132 + c)       = make_float2(acc[mt][nt][0], acc[mt][nt][1]);
            *(float2*)(cs + (r + 8) * 132 + c) = make_float2(acc[mt][nt][2], acc[mt][nt][3]);
        }
    }
    __syncthreads();

    const int c4 = (tid & 31) * 4;
    const float4 b4 = *(const float4*)(bias + col0 + c4);
#pragma unroll
    for (int i = 0; i < 16; i++) {
        const int row = (tid >> 5) + i * 8;
        float4 v = *(const float4*)(cs + row * 132 + c4);
        v.x += b4.x; v.y += b4.y; v.z += b4.z; v.w += b4.w;
        if (BF16OUT) {
            u32 h0, l0, h1, l1;
            split2(v.x, v.y, h0, l0);
            split2(v.z, v.w, h1, l1);
            const size_t off = (size_t)(row0 + row) * CDIM + col0 + c4;
            uint2 hh; hh.x = h0; hh.y = h1;
            uint2 ll; ll.x = l0; ll.y = l1;
            *(uint2*)(Ch + off) = hh;
            *(uint2*)(Cl + off) = ll;
        } else {
            *(float4*)(C + (size_t)(row0 + row) * CDIM + col0 + c4) = v;
        }
    }
}

// QKV fused: grid (MROWS/128, 6); which = blockIdx.y>>1, col0 = (y&1)*128
__global__ __launch_bounds__(256, 2) void gemm_qkv_kernel(
    const f16* __restrict__ qh, const f16* __restrict__ ql,
    const f16* __restrict__ kvh, const f16* __restrict__ kvl,
    const f16* __restrict__ wbase,
    const float* __restrict__ bq, const float* __restrict__ bk,
    const float* __restrict__ bv,
    bf16* __restrict__ qph, bf16* __restrict__ qpl,
    bf16* __restrict__ kph, bf16* __restrict__ kpl,
    bf16* __restrict__ vph, bf16* __restrict__ vpl)
{
    extern __shared__ char smem[];
    const int j = blockIdx.y;
    const int which = j >> 1;
    const int col0 = (j & 1) * 128;
    const f16* Ah = (which == 0) ? qh : kvh;
    const f16* Al = (which == 0) ? ql : kvl;
    const f16* B  = wbase + (size_t)which * CDIM * CDIM;
    const float* bias = (which == 0) ? bq : (which == 1) ? bk : bv;
    bf16* Ch = (which == 0) ? qph : (which == 1) ? kph : vph;
    bf16* Cl = (which == 0) ? qpl : (which == 1) ? kpl : vpl;
    gemm_body<true>(Ah, Al, B, bias, nullptr, Ch, Cl,
                    blockIdx.x * 128, col0, smem);
}

__global__ __launch_bounds__(256, 2) void gemm_o_kernel(
    const f16* __restrict__ xah, const f16* __restrict__ xal,
    const f16* __restrict__ wo,
    const float* __restrict__ bo, float* __restrict__ out)
{
    extern __shared__ char smem[];
    gemm_body<false>(xah, xal, wo, bo, out, nullptr, nullptr,
                     blockIdx.x * 128, blockIdx.y * 128, smem);
}

// ---------------------------------------------------------------------------
// Tensor-core windowed attention (bf16x3 QK^T and PV) — unchanged from R13
// except the output is written as fp16 hi/lo for the fp16 O-GEMM.
// ---------------------------------------------------------------------------
#define ATT_QH 0
#define ATT_QL 5120
#define ATT_KH 10240
#define ATT_KL 15360
#define ATT_VH 20480
#define ATT_VL 25600
#define ATT_SMEM 30720

__global__ __launch_bounds__(128) void attn_kernel(
    const bf16* __restrict__ qph, const bf16* __restrict__ qpl,
    const bf16* __restrict__ kph, const bf16* __restrict__ kpl,
    const bf16* __restrict__ vph, const bf16* __restrict__ vpl,
    f16* __restrict__ xah, f16* __restrict__ xal)
{
    __shared__ char smem[ATT_SMEM];
    const u32 sb = smem_u32(smem);
    const int win = blockIdx.x, h = blockIdx.y, b = blockIdx.z;
    const int wr = win >> 4, wc = win & 15;
    const int tid = threadIdx.x, lane = tid & 31, wq = tid >> 5;

    // ---- staging: pure uint4 copies
    {
        const int tok = tid >> 1;
        const int dh  = (tid & 1) << 4;
        const int tokn = (wr * WS + (tok >> 3)) * HGRID + wc * WS + (tok & 7);
        const size_t gb = ((size_t)b * NTOK + tokn) * CDIM + h * HD + dh;
        const u32 srow = tok * 80 + dh * 2;

        const bf16* srcs[6] = {qph + gb, qpl + gb, kph + gb,
                               kpl + gb, vph + gb, vpl + gb};
        const int offs[6] = {ATT_QH, ATT_QL, ATT_KH, ATT_KL, ATT_VH, ATT_VL};
#pragma unroll
        for (int m = 0; m < 6; m++) {
            const uint4* g = (const uint4*)srcs[m];
            *(uint4*)(smem + offs[m] + srow)      = g[0];
            *(uint4*)(smem + offs[m] + srow + 16) = g[1];
        }
    }
    __syncthreads();

    // ---- S = Q K^T (bf16x3)
    const u32 aLaneQ = sb + (u32)((wq * 16 + (lane & 15)) * 80 + ((lane >> 4) & 1) * 16);
    const u32 bLaneK = sb + (u32)((lane & 7) * 80 + ((lane >> 3) & 1) * 16);

    float sc[8][4];
#pragma unroll
    for (int nt = 0; nt < 8; nt++)
#pragma unroll
        for (int e = 0; e < 4; e++) sc[nt][e] = 0.f;

#pragma unroll
    for (int ks = 0; ks < 2; ks++) {
        u32 ah[4], al[4];
        ldmA(ah, aLaneQ + ATT_QH + ks * 32);
        ldmA(al, aLaneQ + ATT_QL + ks * 32);
#pragma unroll
        for (int nt = 0; nt < 8; nt++) {
            u32 bh[2], bl[2];
            ldmB(bh, bLaneK + ATT_KH + nt * 640 + ks * 32);
            ldmB(bl, bLaneK + ATT_KL + nt * 640 + ks * 32);
            mma16816(sc[nt], ah, bh);
            mma16816(sc[nt], ah, bl);
            mma16816(sc[nt], al, bh);
        }
    }

    // ---- softmax
    const float scale = 0.17677669529663687f;  // 32^-0.5
    float sum0 = 0.f, sum1 = 0.f;
#pragma unroll
    for (int nt = 0; nt < 8; nt++) {
        float p0 = __expf(sc[nt][0] * scale);
        float p1 = __expf(sc[nt][1] * scale);
        float p2 = __expf(sc[nt][2] * scale);
        float p3 = __expf(sc[nt][3] * scale);
        sc[nt][0] = p0; sc[nt][1] = p1; sc[nt][2] = p2; sc[nt][3] = p3;
        sum0 += p0 + p1; sum1 += p2 + p3;
    }
    sum0 += __shfl_xor_sync(0xFFFFFFFFu, sum0, 1);
    sum0 += __shfl_xor_sync(0xFFFFFFFFu, sum0, 2);
    sum1 += __shfl_xor_sync(0xFFFFFFFFu, sum1, 1);
    sum1 += __shfl_xor_sync(0xFFFFFFFFu, sum1, 2);
    const float inv0 = 1.0f / sum0, inv1 = 1.0f / sum1;

    // ---- O = P V (bf16x3), V via transposed ldmatrix
    float oc[4][4];
#pragma unroll
    for (int nt = 0; nt < 4; nt++)
#pragma unroll
        for (int e = 0; e < 4; e++) oc[nt][e] = 0.f;

#pragma unroll
    for (int kk = 0; kk < 4; kk++) {
        u32 pah[4], pal[4];
        split2(sc[2*kk][0],   sc[2*kk][1],   pah[0], pal[0]);
        split2(sc[2*kk][2],   sc[2*kk][3],   pah[1], pal[1]);
        split2(sc[2*kk+1][0], sc[2*kk+1][1], pah[2], pal[2]);
        split2(sc[2*kk+1][2], sc[2*kk+1][3], pah[3], pal[3]);
        const u32 vRow = sb + (u32)((kk * 16 + (lane & 15)) * 80);
#pragma unroll
        for (int nt = 0; nt < 4; nt++) {
            u32 bh[2], bl[2];
            ldmBT(bh, vRow + ATT_VH + nt * 16);
            ldmBT(bl, vRow + ATT_VL + nt * 16);
            mma16816(oc[nt], pah, bh);
            mma16816(oc[nt], pah, bl);
            mma16816(oc[nt], pal, bh);
        }
    }

    // ---- normalize + write fp16 hi/lo directly (u32 pairs)
    const int r0 = wq * 16 + (lane >> 2);
    const int r1 = r0 + 8;
    const int t0 = (wr * WS + (r0 >> 3)) * HGRID + wc * WS + (r0 & 7);
    const int t1 = (wr * WS + (r1 >> 3)) * HGRID + wc * WS + (r1 & 7);
    const size_t o0 = ((size_t)b * NTOK + t0) * CDIM + h * HD + (lane & 3) * 2;
    const size_t o1 = ((size_t)b * NTOK + t1) * CDIM + h * HD + (lane & 3) * 2;
#pragma unroll
    for (int nt = 0; nt < 4; nt++) {
        u32 hw0, lw0, hw1, lw1;
        split2h(oc[nt][0] * inv0, oc[nt][1] * inv0, hw0, lw0);
        split2h(oc[nt][2] * inv1, oc[nt][3] * inv1, hw1, lw1);
        *(u32*)(xah + o0 + nt * 8) = hw0;
        *(u32*)(xal + o0 + nt * 8) = lw0;
        *(u32*)(xah + o1 + nt * 8) = hw1;
        *(u32*)(xal + o1 + nt * 8) = lw1;
    }
}

// ---------------------------------------------------------------------------
// launch
// ---------------------------------------------------------------------------
extern "C" void kernel_launch(void* const* d_in, const int* in_sizes, int n_in,
                              void* d_out, int out_size)
{
    const float* q  = (const float*)d_in[0];
    const float* kv = (const float*)d_in[1];
    const float* Wq = (const float*)d_in[2];
    const float* bq = (const float*)d_in[3];
    const float* Wk = (const float*)d_in[4];
    const float* bk = (const float*)d_in[5];
    const float* Wv = (const float*)d_in[6];
    const float* bv = (const float*)d_in[7];
    const float* Wo = (const float*)d_in[8];
    const float* bo = (const float*)d_in[9];
    float* out = (float*)d_out;

    void *p_qph, *p_qpl, *p_kph, *p_kpl, *p_vph, *p_vpl;
    void *p_qh, *p_ql, *p_kvh, *p_kvl, *p_xah, *p_xal, *p_w;
    cudaGetSymbolAddress(&p_qph, g_qph4);
    cudaGetSymbolAddress(&p_qpl, g_qpl4);
    cudaGetSymbolAddress(&p_kph, g_kph4);
    cudaGetSymbolAddress(&p_kpl, g_kpl4);
    cudaGetSymbolAddress(&p_vph, g_vph4);
    cudaGetSymbolAddress(&p_vpl, g_vpl4);
    cudaGetSymbolAddress(&p_qh, g_qh4);
    cudaGetSymbolAddress(&p_ql, g_ql4);
    cudaGetSymbolAddress(&p_kvh, g_kvh4);
    cudaGetSymbolAddress(&p_kvl, g_kvl4);
    cudaGetSymbolAddress(&p_xah, g_xah4);
    cudaGetSymbolAddress(&p_xal, g_xal4);
    cudaGetSymbolAddress(&p_w, g_w4);

    f16* wbuf = (f16*)p_w;
    const size_t WSZ = (size_t)CDIM * CDIM;
    f16* wo = wbuf + 3 * WSZ;

    cudaFuncSetAttribute(gemm_qkv_kernel,
                         cudaFuncAttributeMaxDynamicSharedMemorySize, GSMEM_TOTAL);
    cudaFuncSetAttribute(gemm_o_kernel,
                         cudaFuncAttributeMaxDynamicSharedMemorySize, GSMEM_TOTAL);

    convw_kernel<<<4 * 256, 256>>>(Wq, Wk, Wv, Wo, wbuf);

    conv_hilo_kernel<<<2 * 8192, 256>>>((const uint4*)q, (const uint4*)kv,
                                        (uint4*)p_qh, (uint4*)p_ql,
                                        (uint4*)p_kvh, (uint4*)p_kvl);

    dim3 qkvGrid(MROWS / 128, 6);
    gemm_qkv_kernel<<<qkvGrid, 256, GSMEM_TOTAL>>>(
        (const f16*)p_qh, (const f16*)p_ql,
        (const f16*)p_kvh, (const f16*)p_kvl,
        wbuf, bq, bk, bv,
        (bf16*)p_qph, (bf16*)p_qpl,
        (bf16*)p_kph, (bf16*)p_kpl,
        (bf16*)p_vph, (bf16*)p_vpl);

    dim3 agrid(NWIN, NHEAD, BATCH);
    attn_kernel<<<agrid, 128>>>(
        (const bf16*)p_qph, (const bf16*)p_qpl,
        (const bf16*)p_kph, (const bf16*)p_kpl,
        (const bf16*)p_vph, (const bf16*)p_vpl,
        (f16*)p_xah, (f16*)p_xal);

    dim3 ogrid(MROWS / 128, 2);
    gemm_o_kernel<<<ogrid, 256, GSMEM_TOTAL>>>(
        (const f16*)p_xah, (const f16*)p_xal, wo, bo, out);
}

// round 17
// speedup vs baseline: 1.4542x; 1.4542x over previous
#include <cuda_runtime.h>
#include <cuda_bf16.h>
#include <cuda_fp16.h>
#include <cstdint>

// B=4, N=16384 (128x128), C=256, heads=8, hd=32, window=8 (64 tokens/window)
#define BATCH 4
#define NTOK  16384
#define CDIM  256
#define MROWS (BATCH * NTOK)   // 65536
#define HGRID 128
#define NHEAD 8
#define HD    32
#define WS    8
#define NWIN  256

typedef unsigned long long u64;
typedef unsigned int u32;
typedef __nv_bfloat16 bf16;
typedef __half f16;

// ---------------------------------------------------------------------------
// sm80-class tensor-core helpers (valid on plain sm_103 PTX target)
// ---------------------------------------------------------------------------
__device__ __forceinline__ u32 smem_u32(const void* p) {
    u32 a; asm("{ .reg .u64 t; cvta.to.shared.u64 t, %1; cvt.u32.u64 %0, t; }"
               : "=r"(a) : "l"(p));
    return a;
}
__device__ __forceinline__ void cp16(u32 s, const void* g) {
    asm volatile("cp.async.cg.shared.global [%0], [%1], 16;" :: "r"(s), "l"(g));
}
#define CP_COMMIT() asm volatile("cp.async.commit_group;" ::: "memory")
#define CP_WAIT(n)  asm volatile("cp.async.wait_group %0;" :: "n"(n) : "memory")

__device__ __forceinline__ void ldmA(u32* a, u32 addr) {
    asm volatile("ldmatrix.sync.aligned.m8n8.x4.shared.b16 {%0,%1,%2,%3}, [%4];"
        : "=r"(a[0]), "=r"(a[1]), "=r"(a[2]), "=r"(a[3]) : "r"(addr));
}
__device__ __forceinline__ void ldmB(u32* b, u32 addr) {
    asm volatile("ldmatrix.sync.aligned.m8n8.x2.shared.b16 {%0,%1}, [%2];"
        : "=r"(b[0]), "=r"(b[1]) : "r"(addr));
}
__device__ __forceinline__ void ldmBT(u32* b, u32 addr) {
    asm volatile("ldmatrix.sync.aligned.m8n8.x2.trans.shared.b16 {%0,%1}, [%2];"
        : "=r"(b[0]), "=r"(b[1]) : "r"(addr));
}
// bf16 mma (attention)
__device__ __forceinline__ void mma16816(float* d, const u32* a, const u32* b) {
    asm volatile("mma.sync.aligned.m16n8k16.row.col.f32.bf16.bf16.f32 "
        "{%0,%1,%2,%3}, {%4,%5,%6,%7}, {%8,%9}, {%0,%1,%2,%3};"
        : "+f"(d[0]), "+f"(d[1]), "+f"(d[2]), "+f"(d[3])
        : "r"(a[0]), "r"(a[1]), "r"(a[2]), "r"(a[3]), "r"(b[0]), "r"(b[1]));
}
// fp16 mma (projections)
__device__ __forceinline__ void mma16816h(float* d, const u32* a, const u32* b) {
    asm volatile("mma.sync.aligned.m16n8k16.row.col.f32.f16.f16.f32 "
        "{%0,%1,%2,%3}, {%4,%5,%6,%7}, {%8,%9}, {%0,%1,%2,%3};"
        : "+f"(d[0]), "+f"(d[1]), "+f"(d[2]), "+f"(d[3])
        : "r"(a[0]), "r"(a[1]), "r"(a[2]), "r"(a[3]), "r"(b[0]), "r"(b[1]));
}

// split two floats into packed bf16 hi and lo words
__device__ __forceinline__ void split2(float x0, float x1, u32 &h, u32 &l) {
    bf16 h0 = __float2bfloat16(x0), h1 = __float2bfloat16(x1);
    bf16 l0 = __float2bfloat16(x0 - __bfloat162float(h0));
    bf16 l1 = __float2bfloat16(x1 - __bfloat162float(h1));
    __nv_bfloat162 hp; hp.x = h0; hp.y = h1;
    __nv_bfloat162 lp; lp.x = l0; lp.y = l1;
    h = *(u32*)&hp; l = *(u32*)&lp;
}
// split two floats into packed fp16 hi and lo words
__device__ __forceinline__ void split2h(float x0, float x1, u32 &h, u32 &l) {
    f16 h0 = __float2half_rn(x0), h1 = __float2half_rn(x1);
    f16 l0 = __float2half_rn(x0 - __half2float(h0));
    f16 l1 = __float2half_rn(x1 - __half2float(h1));
    __half2 hp; hp.x = h0; hp.y = h1;
    __half2 lp; lp.x = l0; lp.y = l1;
    h = *(u32*)&hp; l = *(u32*)&lp;
}

// ---------------------------------------------------------------------------
// Scratch (device globals, 16B-aligned via uint4)
// ---------------------------------------------------------------------------
__device__ uint4 g_qph4[MROWS * CDIM / 8];      // q projection bf16 hi/lo (attn in)
__device__ uint4 g_qpl4[MROWS * CDIM / 8];
__device__ uint4 g_kph4[MROWS * CDIM / 8];
__device__ uint4 g_kpl4[MROWS * CDIM / 8];
__device__ uint4 g_vph4[MROWS * CDIM / 8];
__device__ uint4 g_vpl4[MROWS * CDIM / 8];
__device__ uint4 g_qh4[MROWS * CDIM / 8];       // input q  fp16 hi/lo
__device__ uint4 g_ql4[MROWS * CDIM / 8];
__device__ uint4 g_kvh4[MROWS * CDIM / 8];      // input kv fp16 hi/lo
__device__ uint4 g_kvl4[MROWS * CDIM / 8];
__device__ uint4 g_xah4[MROWS * CDIM / 8];      // attn out fp16 hi/lo
__device__ uint4 g_xal4[MROWS * CDIM / 8];
__device__ uint4 g_w4[4][CDIM * CDIM / 8];      // [which W] single fp16, transposed [n][k]

// ---------------------------------------------------------------------------
// W convert + transpose, single fp16, all 4 weights in one launch
// ---------------------------------------------------------------------------
__global__ void convw_kernel(const float* __restrict__ W0, const float* __restrict__ W1,
                             const float* __restrict__ W2, const float* __restrict__ W3,
                             f16* __restrict__ wt)
{
    const int w = blockIdx.x >> 8, k = blockIdx.x & 255, n = threadIdx.x;
    const float* W = (w == 0) ? W0 : (w == 1) ? W1 : (w == 2) ? W2 : W3;
    f16* wT = wt + (size_t)w * CDIM * CDIM;
    wT[n * CDIM + k] = __float2half_rn(W[k * CDIM + n]);
}

// ---------------------------------------------------------------------------
// A convert: q AND kv in one launch. fp32 -> fp16 hi/lo, 8 floats/thread
// ---------------------------------------------------------------------------
__global__ __launch_bounds__(256) void conv_hilo_kernel(
    const uint4* __restrict__ inq, const uint4* __restrict__ inkv,
    uint4* __restrict__ qh, uint4* __restrict__ ql,
    uint4* __restrict__ kvh, uint4* __restrict__ kvl)
{
    const int which = blockIdx.x >> 13;
    const int i = (blockIdx.x & 8191) * 256 + threadIdx.x;
    const uint4* in = which ? inkv : inq;
    uint4* oh = which ? kvh : qh;
    uint4* ol = which ? kvl : ql;

    uint4 a = in[2 * i], b = in[2 * i + 1];
    float f[8] = {__uint_as_float(a.x), __uint_as_float(a.y),
                  __uint_as_float(a.z), __uint_as_float(a.w),
                  __uint_as_float(b.x), __uint_as_float(b.y),
                  __uint_as_float(b.z), __uint_as_float(b.w)};
    u32 hw[4], lw[4];
#pragma unroll
    for (int p = 0; p < 4; p++) split2h(f[2 * p], f[2 * p + 1], hw[p], lw[p]);
    oh[i] = make_uint4(hw[0], hw[1], hw[2], hw[3]);
    ol[i] = make_uint4(lw[0], lw[1], lw[2], lw[3]);
}

// ---------------------------------------------------------------------------
// fp16 2-pass GEMM: C = (Ah+Al)[M,256] @ B^T + bias, B single fp16.
// CTA 128x128, 8 warps, 2 CTAs/SM. K chunks of 32, cp.async double-buffered,
// 80B rows. Per k16: ldm B, Ah -> Ah*B ; ldm Al -> Al*B  (12 ldm, 32 mma).
// ---------------------------------------------------------------------------
#define KC     32
#define RSTR   80
#define MATSZ  (128 * RSTR)           // 10240
#define OFF_AH 0
#define OFF_AL MATSZ
#define OFF_B  (2 * MATSZ)
#define BUFSZ  (3 * MATSZ)            // 30720
#define GSMEM_TOTAL 69632             // max(2*BUFSZ, epilogue 128*132*4)

template<bool BF16OUT>
__device__ __forceinline__ void gemm_body(
    const f16* __restrict__ Ah, const f16* __restrict__ Al,
    const f16* __restrict__ BT,
    const float* __restrict__ bias,
    float* __restrict__ C, bf16* __restrict__ Ch, bf16* __restrict__ Cl,
    int row0, int col0, char* smem)
{
    const u32 sb = smem_u32(smem);
    const int tid  = threadIdx.x;
    const int lane = tid & 31;
    const int wid  = tid >> 5;
    const int wm   = wid >> 2;
    const int wn   = wid & 3;

    const int st_row = tid >> 1;
    const int st_ch  = (tid & 1) << 4;
    const f16* gA_h = Ah + (size_t)(row0 + st_row) * CDIM + st_ch;
    const f16* gA_l = Al + (size_t)(row0 + st_row) * CDIM + st_ch;
    const f16* gB   = BT + (size_t)(col0 + st_row) * CDIM + st_ch;
    const u32 st_s = st_row * RSTR + st_ch * 2;

    auto stage = [&](int s, int kc) {
        const u32 base = sb + s * BUFSZ + st_s;
        const int gk = kc * KC;
        cp16(base + OFF_AH,      gA_h + gk);
        cp16(base + OFF_AH + 16, gA_h + gk + 8);
        cp16(base + OFF_AL,      gA_l + gk);
        cp16(base + OFF_AL + 16, gA_l + gk + 8);
        cp16(base + OFF_B,       gB + gk);
        cp16(base + OFF_B + 16,  gB + gk + 8);
    };

    float acc[4][4][4];
#pragma unroll
    for (int mt = 0; mt < 4; mt++)
#pragma unroll
        for (int nt = 0; nt < 4; nt++)
#pragma unroll
            for (int e = 0; e < 4; e++) acc[mt][nt][e] = 0.f;

    const u32 aLane = (u32)((wm * 64 + (lane & 15)) * RSTR + ((lane >> 4) << 4));
    const u32 bLane = (u32)((wn * 32 + (lane & 7)) * RSTR + (((lane >> 3) & 1) << 4));

    stage(0, 0); CP_COMMIT();
    stage(1, 1); CP_COMMIT();

#pragma unroll
    for (int kc = 0; kc < 8; kc++) {
        if (kc < 7) CP_WAIT(1); else CP_WAIT(0);
        __syncthreads();

        const u32 sbuf = sb + (kc & 1) * BUFSZ;
#pragma unroll
        for (int k16 = 0; k16 < 2; k16++) {
            const u32 aAddr = sbuf + aLane + k16 * 32;
            const u32 bAddr = sbuf + bLane + k16 * 32;
            u32 ah[4][4], al[4][4], bb[4][2];
#pragma unroll
            for (int nt = 0; nt < 4; nt++) ldmB(bb[nt], bAddr + OFF_B + nt * (8 * RSTR));
#pragma unroll
            for (int mt = 0; mt < 4; mt++) ldmA(ah[mt], aAddr + OFF_AH + mt * (16 * RSTR));
#pragma unroll
            for (int mt = 0; mt < 4; mt++)
#pragma unroll
                for (int nt = 0; nt < 4; nt++) mma16816h(acc[mt][nt], ah[mt], bb[nt]);
#pragma unroll
            for (int mt = 0; mt < 4; mt++) ldmA(al[mt], aAddr + OFF_AL + mt * (16 * RSTR));
#pragma unroll
            for (int mt = 0; mt < 4; mt++)
#pragma unroll
                for (int nt = 0; nt < 4; nt++) mma16816h(acc[mt][nt], al[mt], bb[nt]);
        }
        __syncthreads();
        if (kc < 6) { stage(kc & 1, kc + 2); CP_COMMIT(); }
    }

    // ---- epilogue via smem for coalesced stores (128 x 132 fp32)
    float* cs = (float*)smem;
#pragma unroll
    for (int mt = 0; mt < 4; mt++) {
        const int r = wm * 64 + mt * 16 + (lane >> 2);
#pragma unroll
        for (int nt = 0; nt < 4; nt++) {
            const int c = wn * 32 + nt * 8 + (lane & 3) * 2;
            *(float2*)(cs + r * 132 + c)       = make_float2(acc[mt][nt][0], acc[mt][nt][1]);
            *(float2*)(cs + (r + 8) * 132 + c) = make_float2(acc[mt][nt][2], acc[mt][nt][3]);
        }
    }
    __syncthreads();

    const int c4 = (tid & 31) * 4;
    const float4 b4 = *(const float4*)(bias + col0 + c4);
#pragma unroll
    for (int i = 0; i < 16; i++) {
        const int row = (tid >> 5) + i * 8;
        float4 v = *(const float4*)(cs + row * 132 + c4);
        v.x += b4.x; v.y += b4.y; v.z += b4.z; v.w += b4.w;
        if (BF16OUT) {
            u32 h0, l0, h1, l1;
            split2(v.x, v.y, h0, l0);
            split2(v.z, v.w, h1, l1);
            const size_t off = (size_t)(row0 + row) * CDIM + col0 + c4;
            uint2 hh; hh.x = h0; hh.y = h1;
            uint2 ll; ll.x = l0; ll.y = l1;
            *(uint2*)(Ch + off) = hh;
            *(uint2*)(Cl + off) = ll;
        } else {
            *(float4*)(C + (size_t)(row0 + row) * CDIM + col0 + c4) = v;
        }
    }
}

// QKV fused: grid (MROWS/128, 6); which = blockIdx.y>>1, col0 = (y&1)*128
__global__ __launch_bounds__(256, 2) void gemm_qkv_kernel(
    const f16* __restrict__ qh, const f16* __restrict__ ql,
    const f16* __restrict__ kvh, const f16* __restrict__ kvl,
    const f16* __restrict__ wbase,
    const float* __restrict__ bq, const float* __restrict__ bk,
    const float* __restrict__ bv,
    bf16* __restrict__ qph, bf16* __restrict__ qpl,
    bf16* __restrict__ kph, bf16* __restrict__ kpl,
    bf16* __restrict__ vph, bf16* __restrict__ vpl)
{
    extern __shared__ char smem[];
    const int j = blockIdx.y;
    const int which = j >> 1;
    const int col0 = (j & 1) * 128;
    const f16* Ah = (which == 0) ? qh : kvh;
    const f16* Al = (which == 0) ? ql : kvl;
    const f16* B  = wbase + (size_t)which * CDIM * CDIM;
    const float* bias = (which == 0) ? bq : (which == 1) ? bk : bv;
    bf16* Ch = (which == 0) ? qph : (which == 1) ? kph : vph;
    bf16* Cl = (which == 0) ? qpl : (which == 1) ? kpl : vpl;
    gemm_body<true>(Ah, Al, B, bias, nullptr, Ch, Cl,
                    blockIdx.x * 128, col0, smem);
}

__global__ __launch_bounds__(256, 2) void gemm_o_kernel(
    const f16* __restrict__ xah, const f16* __restrict__ xal,
    const f16* __restrict__ wo,
    const float* __restrict__ bo, float* __restrict__ out)
{
    extern __shared__ char smem[];
    gemm_body<false>(xah, xal, wo, bo, out, nullptr, nullptr,
                     blockIdx.x * 128, blockIdx.y * 128, smem);
}

// ---------------------------------------------------------------------------
// Tensor-core windowed attention (bf16x3 QK^T and PV) — unchanged from R13
// except the output is written as fp16 hi/lo for the fp16 O-GEMM.
// ---------------------------------------------------------------------------
#define ATT_QH 0
#define ATT_QL 5120
#define ATT_KH 10240
#define ATT_KL 15360
#define ATT_VH 20480
#define ATT_VL 25600
#define ATT_SMEM 30720

__global__ __launch_bounds__(128) void attn_kernel(
    const bf16* __restrict__ qph, const bf16* __restrict__ qpl,
    const bf16* __restrict__ kph, const bf16* __restrict__ kpl,
    const bf16* __restrict__ vph, const bf16* __restrict__ vpl,
    f16* __restrict__ xah, f16* __restrict__ xal)
{
    __shared__ char smem[ATT_SMEM];
    const u32 sb = smem_u32(smem);
    const int win = blockIdx.x, h = blockIdx.y, b = blockIdx.z;
    const int wr = win >> 4, wc = win & 15;
    const int tid = threadIdx.x, lane = tid & 31, wq = tid >> 5;

    // ---- staging: pure uint4 copies
    {
        const int tok = tid >> 1;
        const int dh  = (tid & 1) << 4;
        const int tokn = (wr * WS + (tok >> 3)) * HGRID + wc * WS + (tok & 7);
        const size_t gb = ((size_t)b * NTOK + tokn) * CDIM + h * HD + dh;
        const u32 srow = tok * 80 + dh * 2;

        const bf16* srcs[6] = {qph + gb, qpl + gb, kph + gb,
                               kpl + gb, vph + gb, vpl + gb};
        const int offs[6] = {ATT_QH, ATT_QL, ATT_KH, ATT_KL, ATT_VH, ATT_VL};
#pragma unroll
        for (int m = 0; m < 6; m++) {
            const uint4* g = (const uint4*)srcs[m];
            *(uint4*)(smem + offs[m] + srow)      = g[0];
            *(uint4*)(smem + offs[m] + srow + 16) = g[1];
        }
    }
    __syncthreads();

    // ---- S = Q K^T (bf16x3)
    const u32 aLaneQ = sb + (u32)((wq * 16 + (lane & 15)) * 80 + ((lane >> 4) & 1) * 16);
    const u32 bLaneK = sb + (u32)((lane & 7) * 80 + ((lane >> 3) & 1) * 16);

    float sc[8][4];
#pragma unroll
    for (int nt = 0; nt < 8; nt++)
#pragma unroll
        for (int e = 0; e < 4; e++) sc[nt][e] = 0.f;

#pragma unroll
    for (int ks = 0; ks < 2; ks++) {
        u32 ah[4], al[4];
        ldmA(ah, aLaneQ + ATT_QH + ks * 32);
        ldmA(al, aLaneQ + ATT_QL + ks * 32);
#pragma unroll
        for (int nt = 0; nt < 8; nt++) {
            u32 bh[2], bl[2];
            ldmB(bh, bLaneK + ATT_KH + nt * 640 + ks * 32);
            ldmB(bl, bLaneK + ATT_KL + nt * 640 + ks * 32);
            mma16816(sc[nt], ah, bh);
            mma16816(sc[nt], ah, bl);
            mma16816(sc[nt], al, bh);
        }
    }

    // ---- softmax
    const float scale = 0.17677669529663687f;  // 32^-0.5
    float sum0 = 0.f, sum1 = 0.f;
#pragma unroll
    for (int nt = 0; nt < 8; nt++) {
        float p0 = __expf(sc[nt][0] * scale);
        float p1 = __expf(sc[nt][1] * scale);
        float p2 = __expf(sc[nt][2] * scale);
        float p3 = __expf(sc[nt][3] * scale);
        sc[nt][0] = p0; sc[nt][1] = p1; sc[nt][2] = p2; sc[nt][3] = p3;
        sum0 += p0 + p1; sum1 += p2 + p3;
    }
    sum0 += __shfl_xor_sync(0xFFFFFFFFu, sum0, 1);
    sum0 += __shfl_xor_sync(0xFFFFFFFFu, sum0, 2);
    sum1 += __shfl_xor_sync(0xFFFFFFFFu, sum1, 1);
    sum1 += __shfl_xor_sync(0xFFFFFFFFu, sum1, 2);
    const float inv0 = 1.0f / sum0, inv1 = 1.0f / sum1;

    // ---- O = P V (bf16x3), V via transposed ldmatrix
    float oc[4][4];
#pragma unroll
    for (int nt = 0; nt < 4; nt++)
#pragma unroll
        for (int e = 0; e < 4; e++) oc[nt][e] = 0.f;

#pragma unroll
    for (int kk = 0; kk < 4; kk++) {
        u32 pah[4], pal[4];
        split2(sc[2*kk][0],   sc[2*kk][1],   pah[0], pal[0]);
        split2(sc[2*kk][2],   sc[2*kk][3],   pah[1], pal[1]);
        split2(sc[2*kk+1][0], sc[2*kk+1][1], pah[2], pal[2]);
        split2(sc[2*kk+1][2], sc[2*kk+1][3], pah[3], pal[3]);
        const u32 vRow = sb + (u32)((kk * 16 + (lane & 15)) * 80);
#pragma unroll
        for (int nt = 0; nt < 4; nt++) {
            u32 bh[2], bl[2];
            ldmBT(bh, vRow + ATT_VH + nt * 16);
            ldmBT(bl, vRow + ATT_VL + nt * 16);
            mma16816(oc[nt], pah, bh);
            mma16816(oc[nt], pah, bl);
            mma16816(oc[nt], pal, bh);
        }
    }

    // ---- normalize + write fp16 hi/lo directly (u32 pairs)
    const int r0 = wq * 16 + (lane >> 2);
    const int r1 = r0 + 8;
    const int t0 = (wr * WS + (r0 >> 3)) * HGRID + wc * WS + (r0 & 7);
    const int t1 = (wr * WS + (r1 >> 3)) * HGRID + wc * WS + (r1 & 7);
    const size_t o0 = ((size_t)b * NTOK + t0) * CDIM + h * HD + (lane & 3) * 2;
    const size_t o1 = ((size_t)b * NTOK + t1) * CDIM + h * HD + (lane & 3) * 2;
#pragma unroll
    for (int nt = 0; nt < 4; nt++) {
        u32 hw0, lw0, hw1, lw1;
        split2h(oc[nt][0] * inv0, oc[nt][1] * inv0, hw0, lw0);
        split2h(oc[nt][2] * inv1, oc[nt][3] * inv1, hw1, lw1);
        *(u32*)(xah + o0 + nt * 8) = hw0;
        *(u32*)(xal + o0 + nt * 8) = lw0;
        *(u32*)(xah + o1 + nt * 8) = hw1;
        *(u32*)(xal + o1 + nt * 8) = lw1;
    }
}

// ---------------------------------------------------------------------------
// launch
// ---------------------------------------------------------------------------
extern "C" void kernel_launch(void* const* d_in, const int* in_sizes, int n_in,
                              void* d_out, int out_size)
{
    const float* q  = (const float*)d_in[0];
    const float* kv = (const float*)d_in[1];
    const float* Wq = (const float*)d_in[2];
    const float* bq = (const float*)d_in[3];
    const float* Wk = (const float*)d_in[4];
    const float* bk = (const float*)d_in[5];
    const float* Wv = (const float*)d_in[6];
    const float* bv = (const float*)d_in[7];
    const float* Wo = (const float*)d_in[8];
    const float* bo = (const float*)d_in[9];
    float* out = (float*)d_out;

    void *p_qph, *p_qpl, *p_kph, *p_kpl, *p_vph, *p_vpl;
    void *p_qh, *p_ql, *p_kvh, *p_kvl, *p_xah, *p_xal, *p_w;
    cudaGetSymbolAddress(&p_qph, g_qph4);
    cudaGetSymbolAddress(&p_qpl, g_qpl4);
    cudaGetSymbolAddress(&p_kph, g_kph4);
    cudaGetSymbolAddress(&p_kpl, g_kpl4);
    cudaGetSymbolAddress(&p_vph, g_vph4);
    cudaGetSymbolAddress(&p_vpl, g_vpl4);
    cudaGetSymbolAddress(&p_qh, g_qh4);
    cudaGetSymbolAddress(&p_ql, g_ql4);
    cudaGetSymbolAddress(&p_kvh, g_kvh4);
    cudaGetSymbolAddress(&p_kvl, g_kvl4);
    cudaGetSymbolAddress(&p_xah, g_xah4);
    cudaGetSymbolAddress(&p_xal, g_xal4);
    cudaGetSymbolAddress(&p_w, g_w4);

    f16* wbuf = (f16*)p_w;
    const size_t WSZ = (size_t)CDIM * CDIM;
    f16* wo = wbuf + 3 * WSZ;

    cudaFuncSetAttribute(gemm_qkv_kernel,
                         cudaFuncAttributeMaxDynamicSharedMemorySize, GSMEM_TOTAL);
    cudaFuncSetAttribute(gemm_o_kernel,
                         cudaFuncAttributeMaxDynamicSharedMemorySize, GSMEM_TOTAL);

    convw_kernel<<<4 * 256, 256>>>(Wq, Wk, Wv, Wo, wbuf);

    conv_hilo_kernel<<<2 * 8192, 256>>>((const uint4*)q, (const uint4*)kv,
                                        (uint4*)p_qh, (uint4*)p_ql,
                                        (uint4*)p_kvh, (uint4*)p_kvl);

    dim3 qkvGrid(MROWS / 128, 6);
    gemm_qkv_kernel<<<qkvGrid, 256, GSMEM_TOTAL>>>(
        (const f16*)p_qh, (const f16*)p_ql,
        (const f16*)p_kvh, (const f16*)p_kvl,
        wbuf, bq, bk, bv,
        (bf16*)p_qph, (bf16*)p_qpl,
        (bf16*)p_kph, (bf16*)p_kpl,
        (bf16*)p_vph, (bf16*)p_vpl);

    dim3 agrid(NWIN, NHEAD, BATCH);
    attn_kernel<<<agrid, 128>>>(
        (const bf16*)p_qph, (const bf16*)p_qpl,
        (const bf16*)p_kph, (const bf16*)p_kpl,
        (const bf16*)p_vph, (const bf16*)p_vpl,
        (f16*)p_xah, (f16*)p_xal);

    dim3 ogrid(MROWS / 128, 2);
    gemm_o_kernel<<<ogrid, 256, GSMEM_TOTAL>>>(
        (const f16*)p_xah, (const f16*)p_xal, wo, bo, out);
}